// round 15
// baseline (speedup 1.0000x reference)
#include <cuda_runtime.h>
#include <cuda_bf16.h>

// Shapes (fixed by setup_inputs): B=32, T=512, C=T-1=511, K=8, S=8, d=300
#define BB 32
#define CC 511
#define KK 8
#define SS 8
#define DD 300
#define D4 75      // DD/4 float4 per row
#define D2 150     // DD/2 float2 per row
#define ASTRIDE 512
#define NTILE 16   // pass1 tiles / tail splits of 32 c (power of 2)
#define RSQRT300 0.057735026918962576f

// Scratch (device globals; no allocation allowed)
// g_v padded by one row: last tail split reads row (b*CC+511) with weight 0.
__device__ float g_v[BB * CC * DD + DD];
__device__ float g_a[BB * KK * ASTRIDE];            // a[b][k][c]
__device__ float g_pden[BB * NTILE * KK];           // partial sum of exp(a)
__device__ float g_mpart[BB * NTILE * KK * DD];     // partial unnormalized m'
__device__ unsigned g_ready[BB];                    // pass1 tiles done per b (reset by epilogue)
__device__ unsigned g_cnt2[BB];                     // tail arrivals (wrapping)

// ---------------------------------------------------------------------------
// ONE kernel, grid 1024 x 256 threads.
//   bid <  512 : pass1 tile (proven R14 streaming code). b = bid>>4 so b=0
//                completes earliest. After the tile: fence + g_ready[b]++.
//   bid >= 512 : tail split. Spins until g_ready[b]==16, then computes exp
//                weights + partial m'/pden; 16th arrival (wrapping g_cnt2)
//                runs cosine-sim/softmax/argmax epilogue, writes outputs,
//                and resets g_ready[b]=0 (all waiters already passed).
// Tail loads overlap pass1's streaming of later batches -> g_v is L2-hot.
// ---------------------------------------------------------------------------
__global__ __launch_bounds__(256) void k_fused(const float* __restrict__ ctx,
                                               const float* __restrict__ center,
                                               float* __restrict__ out) {
    const int bid = blockIdx.x;
    const int w = threadIdx.x >> 5;
    const int lane = threadIdx.x & 31;

    if (bid < NTILE * BB) {
        // =================== pass1 tile ===================
        const int b = bid >> 4;
        const int tile = bid & (NTILE - 1);
        __shared__ float4 cen[KK * D4];        // 9600 B

        {
            const float4* cg = reinterpret_cast<const float4*>(center + (size_t)b * KK * DD);
            for (int i = threadIdx.x; i < KK * D4; i += blockDim.x) cen[i] = cg[i];
        }
        __syncthreads();

        const int j0 = lane, j1 = lane + 32, j2 = lane + 64;
        const bool p2 = (j2 < D4);

        int cend = tile * 32 + 32;
        if (cend > CC) cend = CC;

        for (int c = tile * 32 + w; c < cend; c += 8) {
            const float4* p = reinterpret_cast<const float4*>(ctx) + (size_t)(b * CC + c) * (SS * D4);
            float4 a0 = {0.f, 0.f, 0.f, 0.f}, a1 = a0, a2 = a0;
#pragma unroll
            for (int s = 0; s < SS; s++) {
                const float4* ps = p + s * D4;
                float4 x0 = __ldcs(ps + j0);
                float4 x1 = __ldcs(ps + j1);
                a0.x += x0.x; a0.y += x0.y; a0.z += x0.z; a0.w += x0.w;
                a1.x += x1.x; a1.y += x1.y; a1.z += x1.z; a1.w += x1.w;
                if (p2) {
                    float4 x2 = __ldcs(ps + j2);
                    a2.x += x2.x; a2.y += x2.y; a2.z += x2.z; a2.w += x2.w;
                }
            }
            const float sc = 1.0f / (float)SS;
            a0.x *= sc; a0.y *= sc; a0.z *= sc; a0.w *= sc;
            a1.x *= sc; a1.y *= sc; a1.z *= sc; a1.w *= sc;
            a2.x *= sc; a2.y *= sc; a2.z *= sc; a2.w *= sc;

            float4* vp = reinterpret_cast<float4*>(g_v) + (size_t)(b * CC + c) * D4;
            vp[j0] = a0;
            vp[j1] = a1;
            if (p2) vp[j2] = a2;

            float ak[KK];
#pragma unroll
            for (int k = 0; k < KK; k++) {
                float4 c0 = cen[k * D4 + j0];
                float4 c1 = cen[k * D4 + j1];
                float t = a0.x * c0.x + a0.y * c0.y + a0.z * c0.z + a0.w * c0.w
                        + a1.x * c1.x + a1.y * c1.y + a1.z * c1.z + a1.w * c1.w;
                if (p2) {
                    float4 c2 = cen[k * D4 + j2];
                    t += a2.x * c2.x + a2.y * c2.y + a2.z * c2.z + a2.w * c2.w;
                }
#pragma unroll
                for (int off = 16; off > 0; off >>= 1)
                    t += __shfl_xor_sync(0xffffffffu, t, off);
                ak[k] = t;
            }
            if (lane == 0) {
#pragma unroll
                for (int k = 0; k < KK; k++)
                    g_a[(size_t)(b * KK + k) * ASTRIDE + c] = ak[k] * RSQRT300;
            }
        }

        __syncthreads();
        if (threadIdx.x == 0) {
            __threadfence();                       // release g_v / g_a
            atomicAdd(&g_ready[b], 1u);
        }
        return;
    }

    // =================== tail split ===================
    const int jj = bid - NTILE * BB;
    const int b = jj >> 4;
    const int split = jj & (NTILE - 1);
    const int c0 = split * 32;
    const int cn = (CC - c0 < 32) ? (CC - c0) : 32;

    // wait for all 16 pass1 tiles of this b
    if (threadIdx.x == 0) {
        while (*(volatile unsigned*)&g_ready[b] < (unsigned)NTILE)
            __nanosleep(128);
    }
    __syncthreads();
    __threadfence();   // order our subsequent reads after observing the flag

    __shared__ float ew[KK][32];

    // exp weights: 256 entries, one per thread; zero outside cn
    {
        const int k = threadIdx.x >> 5, cc = threadIdx.x & 31;
        float val = 0.f;
        if (cc < cn)
            val = __expf(__ldcg(&g_a[(size_t)(b * KK + k) * ASTRIDE + c0 + cc]));
        ew[k][cc] = val;
    }
    __syncthreads();

    // pden partials
    if (threadIdx.x < KK) {
        const int k = threadIdx.x;
        float s = 0.f;
#pragma unroll
        for (int cc = 0; cc < 32; cc++) s += ew[k][cc];
        g_pden[(b * NTILE + split) * KK + k] = s;
    }

    // partial m': thread covers d = t and (for t < 44) d = t + 256
    for (int d = threadIdx.x; d < DD; d += 256) {
        float acc[KK];
#pragma unroll
        for (int k = 0; k < KK; k++) acc[k] = 0.f;

        const float* vb = g_v + (size_t)(b * CC + c0) * DD + d;
#pragma unroll 8
        for (int cc = 0; cc < 32; cc++) {
            float v = __ldcg(vb + (size_t)cc * DD);  // weight 0 past cn (padded g_v)
#pragma unroll
            for (int k = 0; k < KK; k++)
                acc[k] += ew[k][cc] * v;
        }
        float* mp = g_mpart + (size_t)((b * NTILE + split) * KK) * DD;
#pragma unroll
        for (int k = 0; k < KK; k++) mp[k * DD + d] = acc[k];
    }

    // arrival; last tail block of this b runs the epilogue
    __syncthreads();
    __shared__ int slast;
    if (threadIdx.x == 0) {
        __threadfence();   // publish mpart/pden (release)
        unsigned old = atomicAdd(&g_cnt2[b], 1u);
        slast = ((old & (NTILE - 1)) == (NTILE - 1)) ? 1 : 0;
    }
    __syncthreads();
    if (!slast) return;

    // ---- epilogue: cosine sim for all 8 k (warp per k, 8 warps) ----
    __shared__ float ssv[KK];
    __shared__ float sq[KK];
    __shared__ int sidx;
    {
        const int k = w;
        float num = 0.f, n1 = 0.f, n2 = 0.f;
        const float2* cp2 = reinterpret_cast<const float2*>(center + (size_t)(b * KK + k) * DD);
#pragma unroll
        for (int it = 0; it < 5; it++) {
            const int j = lane + it * 32;
            if (j < D2) {
                float2 cv = cp2[j];
                float2 mm = make_float2(0.f, 0.f);
#pragma unroll
                for (int s = 0; s < NTILE; s++) {
                    const float2* mp = reinterpret_cast<const float2*>(g_mpart)
                                     + (size_t)((b * NTILE + s) * KK + k) * D2;
                    float2 x = __ldcg(mp + j);
                    mm.x += x.x; mm.y += x.y;
                }
                num += cv.x * mm.x + cv.y * mm.y;
                n1  += cv.x * cv.x + cv.y * cv.y;
                n2  += mm.x * mm.x + mm.y * mm.y;
            }
        }
#pragma unroll
        for (int off = 16; off > 0; off >>= 1) {
            num += __shfl_xor_sync(0xffffffffu, num, off);
            n1  += __shfl_xor_sync(0xffffffffu, n1, off);
            n2  += __shfl_xor_sync(0xffffffffu, n2, off);
        }
        if (lane == 0) {
            float dsum = 0.f;
#pragma unroll
            for (int s = 0; s < NTILE; s++)
                dsum += __ldcg(&g_pden[(b * NTILE + s) * KK + k]);
            float invd = 1.0f / dsum;
            float d1 = fmaxf(sqrtf(n1), 1e-8f);
            float d2 = fmaxf(sqrtf(n2) * invd, 1e-8f);
            ssv[k] = (num * invd) / (d1 * d2);
        }
    }
    __syncthreads();

    if (threadIdx.x == 0) {
        float mx = ssv[0]; int id = 0;
#pragma unroll
        for (int i = 1; i < KK; i++)
            if (ssv[i] > mx) { mx = ssv[i]; id = i; }
        float den = 0.f;
#pragma unroll
        for (int i = 0; i < KK; i++) den += __expf(ssv[i] - mx);
        float invden = 1.0f / den;
#pragma unroll
        for (int i = 0; i < KK; i++) sq[i] = __expf(ssv[i] - mx) * invden;
        sidx = id;
    }
    __syncthreads();

    if (threadIdx.x < KK)
        out[BB * DD + b * KK + threadIdx.x] = sq[threadIdx.x];
    if (threadIdx.x < D4) {
        const float4* src = reinterpret_cast<const float4*>(center + (size_t)(b * KK + sidx) * DD);
        float4* dst = reinterpret_cast<float4*>(out + (size_t)b * DD);
        dst[threadIdx.x] = src[threadIdx.x];
    }

    // reset the ready counter for the next graph replay (all 16 tail blocks
    // for this b have already passed their wait -- they arrived on g_cnt2).
    if (threadIdx.x == 0) {
        __threadfence();
        g_ready[b] = 0u;
    }
}

// ---------------------------------------------------------------------------
extern "C" void kernel_launch(void* const* d_in, const int* in_sizes, int n_in,
                              void* d_out, int out_size) {
    // inputs: 0 center_pos(i32), 1 query_token_ids(i32) -- both mathematically dead
    //         2 center_sense_embeddings f32 [32,8,300]
    //         3 context_sense_embeddings f32 [32,511,8,300]
    const float* center = (const float*)d_in[2];
    const float* ctx    = (const float*)d_in[3];
    float* out = (float*)d_out;

    k_fused<<<2 * NTILE * BB, 256>>>(ctx, center, out);
}

// round 16
// speedup vs baseline: 1.2312x; 1.2312x over previous
#include <cuda_runtime.h>
#include <cuda_bf16.h>

// Shapes (fixed by setup_inputs): B=32, T=512, C=T-1=511, K=8, S=8, d=300
#define BB 32
#define CC 511
#define KK 8
#define SS 8
#define DD 300
#define D4 75      // DD/4 float4 per row
#define D2 150     // DD/2 float2 per row
#define TILE_C 32
#define NSPLIT 16  // power of 2 for wrapping counter
#define NPROD 6    // producer warps; warps 6,7 are consumers
#define RSQRT300 0.057735026918962576f

// Scratch (device globals; no allocation allowed)
__device__ float g_pden[BB * NSPLIT * KK];        // partial sum of exp(a)
__device__ float g_mpart[BB * NSPLIT * KK * DD];  // partial unnormalized m'
__device__ unsigned g_cnt[BB];                    // wrapping completion counters

// ---------------------------------------------------------------------------
// Warp-specialized fused kernel. grid (NSPLIT=16, B=32) = 512 blocks, 256 thr.
// Producers (warps 0-5): stream ctx, v=mean_s -> vt smem, dots for 8 k
//   (serial 5-shuffle reduce, R5-proven), publish ew[1..7][ci] then flag
//   ew[0][ci] (exp>0) after __syncwarp + fence. NO phase barrier.
// Consumers (warps 6-7, 64 thr): spin per-c on ew[0][ci], incrementally
//   accumulate m'[k][d] += ew[k][ci]*v[ci][d] (thread owns 4-5 d's) + pden.
//   Consumer work hides fully under the producer stream -> DRAM never idles.
// Then the R10-proven wrapping-counter last-block epilogue.
// ---------------------------------------------------------------------------
__global__ __launch_bounds__(256) void k_main(const float* __restrict__ ctx,
                                              const float* __restrict__ center,
                                              float* __restrict__ out) {
    const int b = blockIdx.y;
    const int tile = blockIdx.x;
    __shared__ float4 cen[KK * D4];        // 9600 B
    __shared__ float4 vt[TILE_C * D4];     // 38400 B
    __shared__ float ew[KK][TILE_C];       // 1024 B  (total 49024 <= 48KB)

    {
        const float4* cg = reinterpret_cast<const float4*>(center + (size_t)b * KK * DD);
        for (int i = threadIdx.x; i < KK * D4; i += blockDim.x) cen[i] = cg[i];
    }
    // zero ew (256 floats, one per thread) -- ew[0][*] doubles as ready flag
    ((float*)ew)[threadIdx.x] = 0.f;
    __syncthreads();

    const int w = threadIdx.x >> 5;
    const int lane = threadIdx.x & 31;

    const int c0 = tile * TILE_C;
    const int cn = (CC - c0 < TILE_C) ? (CC - c0) : TILE_C;

    if (w < NPROD) {
        // =================== producer warps ===================
        const int j0 = lane, j1 = lane + 32, j2 = lane + 64;
        const bool p2 = (j2 < D4);

        for (int ci = w; ci < cn; ci += NPROD) {
            const int c = c0 + ci;
            const float4* p = reinterpret_cast<const float4*>(ctx) + (size_t)(b * CC + c) * (SS * D4);
            float4 a0 = {0.f, 0.f, 0.f, 0.f}, a1 = a0, a2 = a0;
#pragma unroll
            for (int s = 0; s < SS; s++) {
                const float4* ps = p + s * D4;
                float4 x0 = __ldcs(ps + j0);
                float4 x1 = __ldcs(ps + j1);
                a0.x += x0.x; a0.y += x0.y; a0.z += x0.z; a0.w += x0.w;
                a1.x += x1.x; a1.y += x1.y; a1.z += x1.z; a1.w += x1.w;
                if (p2) {
                    float4 x2 = __ldcs(ps + j2);
                    a2.x += x2.x; a2.y += x2.y; a2.z += x2.z; a2.w += x2.w;
                }
            }
            const float sc = 1.0f / (float)SS;
            a0.x *= sc; a0.y *= sc; a0.z *= sc; a0.w *= sc;
            a1.x *= sc; a1.y *= sc; a1.z *= sc; a1.w *= sc;
            a2.x *= sc; a2.y *= sc; a2.z *= sc; a2.w *= sc;

            vt[ci * D4 + j0] = a0;
            vt[ci * D4 + j1] = a1;
            if (p2) vt[ci * D4 + j2] = a2;

            float e0val = 0.f;
#pragma unroll
            for (int k = 0; k < KK; k++) {
                float4 c0v = cen[k * D4 + j0];
                float4 c1v = cen[k * D4 + j1];
                float t = a0.x * c0v.x + a0.y * c0v.y + a0.z * c0v.z + a0.w * c0v.w
                        + a1.x * c1v.x + a1.y * c1v.y + a1.z * c1v.z + a1.w * c1v.w;
                if (p2) {
                    float4 c2v = cen[k * D4 + j2];
                    t += a2.x * c2v.x + a2.y * c2v.y + a2.z * c2v.z + a2.w * c2v.w;
                }
#pragma unroll
                for (int off = 16; off > 0; off >>= 1)
                    t += __shfl_xor_sync(0xffffffffu, t, off);
                if (lane == 0) {
                    float ev = __expf(t * RSQRT300);
                    if (k == 0) e0val = ev;
                    else        ew[k][ci] = ev;
                }
            }
            // publish: all lanes' vt writes ordered before the flag
            __syncwarp();
            if (lane == 0) {
                __threadfence_block();
                ((volatile float*)&ew[0][0])[ci] = e0val;   // ready flag (exp>0)
            }
        }
    } else {
        // =================== consumer warps (64 threads) ===================
        const int ct = threadIdx.x - NPROD * 32;    // 0..63
        const bool has4 = (ct < DD - 256);          // ct < 44
        float acc[5][KK];
#pragma unroll
        for (int j = 0; j < 5; j++)
#pragma unroll
            for (int k = 0; k < KK; k++) acc[j][k] = 0.f;

        for (int ci = 0; ci < cn; ci++) {
            float e0;
            while ((e0 = ((volatile float*)&ew[0][0])[ci]) == 0.f) { }
            __threadfence_block();
            float e[KK];
            e[0] = e0;
#pragma unroll
            for (int k = 1; k < KK; k++) e[k] = ew[k][ci];

            const float* vrow = reinterpret_cast<const float*>(vt + ci * D4);
#pragma unroll
            for (int j = 0; j < 4; j++) {
                float v = vrow[ct + 64 * j];
#pragma unroll
                for (int k = 0; k < KK; k++) acc[j][k] += e[k] * v;
            }
            if (has4) {
                float v = vrow[ct + 256];
#pragma unroll
                for (int k = 0; k < KK; k++) acc[4][k] += e[k] * v;
            }
        }

        float* mp = g_mpart + (size_t)((b * NSPLIT + tile) * KK) * DD;
#pragma unroll
        for (int j = 0; j < 4; j++)
#pragma unroll
            for (int k = 0; k < KK; k++)
                mp[k * DD + ct + 64 * j] = acc[j][k];
        if (has4) {
#pragma unroll
            for (int k = 0; k < KK; k++)
                mp[k * DD + ct + 256] = acc[4][k];
        }

        if (ct < KK) {   // pden by 8 threads (all flags observed set above)
            float s = 0.f;
            for (int cc = 0; cc < cn; cc++) s += ew[ct][cc];
            g_pden[(b * NSPLIT + tile) * KK + ct] = s;
        }
    }

    // ---- Arrival: last tile-block of this b runs the epilogue ----
    __syncthreads();
    __shared__ int slast;
    if (threadIdx.x == 0) {
        __threadfence();   // publish mpart/pden (release)
        unsigned old = atomicAdd(&g_cnt[b], 1u);
        slast = ((old & (NSPLIT - 1)) == (NSPLIT - 1)) ? 1 : 0;
    }
    __syncthreads();
    if (!slast) return;

    // ---- Epilogue (one block per b): cosine sim, warp per k ----
    __shared__ float ssv[KK];
    __shared__ float sq[KK];
    __shared__ int sidx;
    {
        const int k = w;   // 8 warps = 8 senses
        float num = 0.f, n1 = 0.f, n2 = 0.f;
        const float2* cp2 = reinterpret_cast<const float2*>(center + (size_t)(b * KK + k) * DD);
#pragma unroll
        for (int it = 0; it < 5; it++) {
            const int j = lane + it * 32;
            if (j < D2) {
                float2 cv = cp2[j];
                float2 mm = make_float2(0.f, 0.f);
#pragma unroll
                for (int s = 0; s < NSPLIT; s++) {
                    const float2* mp = reinterpret_cast<const float2*>(g_mpart)
                                     + (size_t)((b * NSPLIT + s) * KK + k) * D2;
                    float2 x = __ldcg(mp + j);   // bypass stale L1
                    mm.x += x.x; mm.y += x.y;
                }
                num += cv.x * mm.x + cv.y * mm.y;
                n1  += cv.x * cv.x + cv.y * cv.y;
                n2  += mm.x * mm.x + mm.y * mm.y;
            }
        }
#pragma unroll
        for (int off = 16; off > 0; off >>= 1) {
            num += __shfl_xor_sync(0xffffffffu, num, off);
            n1  += __shfl_xor_sync(0xffffffffu, n1, off);
            n2  += __shfl_xor_sync(0xffffffffu, n2, off);
        }
        if (lane == 0) {
            float dsum = 0.f;
#pragma unroll
            for (int s = 0; s < NSPLIT; s++)
                dsum += __ldcg(&g_pden[(b * NSPLIT + s) * KK + k]);
            float invd = 1.0f / dsum;
            float d1 = fmaxf(sqrtf(n1), 1e-8f);
            float d2 = fmaxf(sqrtf(n2) * invd, 1e-8f);
            ssv[k] = (num * invd) / (d1 * d2);
        }
    }
    __syncthreads();

    if (threadIdx.x == 0) {
        float mx = ssv[0]; int id = 0;
#pragma unroll
        for (int i = 1; i < KK; i++)
            if (ssv[i] > mx) { mx = ssv[i]; id = i; }
        float den = 0.f;
#pragma unroll
        for (int i = 0; i < KK; i++) den += __expf(ssv[i] - mx);
        float invden = 1.0f / den;
#pragma unroll
        for (int i = 0; i < KK; i++) sq[i] = __expf(ssv[i] - mx) * invden;
        sidx = id;
    }
    __syncthreads();

    if (threadIdx.x < KK)
        out[BB * DD + b * KK + threadIdx.x] = sq[threadIdx.x];
    if (threadIdx.x < D4) {
        const float4* src = reinterpret_cast<const float4*>(center + (size_t)(b * KK + sidx) * DD);
        float4* dst = reinterpret_cast<float4*>(out + (size_t)b * DD);
        dst[threadIdx.x] = src[threadIdx.x];
    }
}

// ---------------------------------------------------------------------------
extern "C" void kernel_launch(void* const* d_in, const int* in_sizes, int n_in,
                              void* d_out, int out_size) {
    // inputs: 0 center_pos(i32), 1 query_token_ids(i32) -- both mathematically dead
    //         2 center_sense_embeddings f32 [32,8,300]
    //         3 context_sense_embeddings f32 [32,511,8,300]
    const float* center = (const float*)d_in[2];
    const float* ctx    = (const float*)d_in[3];
    float* out = (float*)d_out;

    k_main<<<dim3(NSPLIT, BB), 256>>>(ctx, center, out);
}